// round 7
// baseline (speedup 1.0000x reference)
#include <cuda_runtime.h>
#include <cstdint>

// Problem dims (fixed)
#define Bv 64
#define Hv 128
#define Wv 128
#define Cv 3
#define Nv 10

#define ROWS 8                 // output rows per CTA
#define SR (ROWS + 4)          // 12 strip rows (halo)
#define SCW 132                // valid strip cols (halo)
#define SC 140                 // padded strip stride (conflict-free frag LDS)
#define BSTRIDE 132            // bounce-buffer row stride (conflict-free STS)
#define NT 128                 // 4 warps

__device__ __forceinline__ uint32_t to_tf32(float v) {
    uint32_t u;
    asm("cvt.rna.tf32.f32 %0, %1;" : "=r"(u) : "f"(v));
    return u;
}

__device__ __forceinline__ void mma_tf32(float c[4], const uint32_t a[4],
                                         uint32_t b0, uint32_t b1) {
    asm("mma.sync.aligned.m16n8k8.row.col.f32.tf32.tf32.f32 "
        "{%0,%1,%2,%3}, {%4,%5,%6,%7}, {%8,%9}, {%0,%1,%2,%3};"
        : "+f"(c[0]), "+f"(c[1]), "+f"(c[2]), "+f"(c[3])
        : "r"(a[0]), "r"(a[1]), "r"(a[2]), "r"(a[3]), "r"(b0), "r"(b1));
}

// out[n][b][c][h][w] = sum_{kh,kw} images[b][h+kh-2][w+kw-2][c] * kernels[b][kh][kw][n]
// GEMM per (b,c): D[pixel, n] = sum_k A[pixel,k] * W[k,n]; K=25 pad 32, N=10 pad 16.
__global__ __launch_bounds__(NT)
void cdna_mma_kernel(const float* __restrict__ images,
                     const float* __restrict__ kernels,
                     float* __restrict__ out)
{
    __shared__ float strip[SR * SC];                    // tf32-rounded image strip
    __shared__ float Wsm[32][16];                       // tf32-rounded weights [k][n]
    __shared__ __align__(16) float buf[4][Nv * BSTRIDE]; // per-warp store bounce

    const int tid  = threadIdx.x;
    const int lane = tid & 31;
    const int wid  = tid >> 5;
    const int g    = lane >> 2;        // 0..7
    const int tg   = lane & 3;         // 0..3

    const int rt = blockIdx.x, c = blockIdx.y, b = blockIdx.z;
    const int r0 = rt * ROWS;

    // ---- stage W: [k=32][n=16], tf32-rounded, pad -> 0 ----
    for (int i = tid; i < 512; i += NT) {
        int k = i >> 4, n = i & 15;
        float v = 0.0f;
        if (k < 25 && n < Nv) v = kernels[(b * 25 + k) * Nv + n];
        Wsm[k][n] = __uint_as_float(to_tf32(v));
    }

    // ---- stage image strip (tf32-rounded, zero-padded halo) ----
    const float* imgb = images + ((size_t)b * Hv) * (Wv * Cv) + c;
    #pragma unroll
    for (int it = 0; it < (SR * SCW + NT - 1) / NT; it++) {
        int i = it * NT + tid;
        if (i < SR * SCW) {
            int r  = i / SCW;
            int cc = i - r * SCW;
            int gh = r0 + r - 2;
            int gw = cc - 2;
            float v = 0.0f;
            if (gh >= 0 && gh < Hv && gw >= 0 && gw < Wv)
                v = imgb[(gh * Wv + gw) * Cv];
            strip[r * SC + cc] = __uint_as_float(to_tf32(v));
        }
    }
    __syncthreads();

    // ---- B fragments ----
    uint32_t bf[4][2][2];
    #pragma unroll
    for (int s = 0; s < 4; s++)
        #pragma unroll
        for (int u = 0; u < 2; u++) {
            bf[s][u][0] = __float_as_uint(Wsm[8 * s + tg][8 * u + g]);
            bf[s][u][1] = __float_as_uint(Wsm[8 * s + tg + 4][8 * u + g]);
        }

    // ---- per-thread tap offsets: col = 8s + tg + 4j -> kh*SC + kw ----
    int off[4][2];
    #pragma unroll
    for (int s = 0; s < 4; s++)
        #pragma unroll
        for (int j = 0; j < 2; j++) {
            int col = 8 * s + tg + 4 * j;
            off[s][j] = (col < 25) ? (col / 5) * SC + (col % 5) : 0;
        }
    const bool t24 = (tg == 0);

    const size_t ns = (size_t)Bv * Cv * Hv * Wv;
    float* outbc = out + (((size_t)b * Cv + c) * Hv + r0) * Wv;
    float* bw = buf[wid];

    // each warp: 2 rows; per row, 8 col-tiles of 16 pixels -> bounce -> coalesced
    for (int lr = wid * 2; lr < wid * 2 + 2; lr++) {
        const float* srow = strip + lr * SC;

        #pragma unroll 2
        for (int ct = 0; ct < 8; ct++) {
            const int p = ct * 16 + g;

            float acc[2][4] = {{0, 0, 0, 0}, {0, 0, 0, 0}};

            #pragma unroll
            for (int s = 0; s < 3; s++) {
                uint32_t a[4];
                a[0] = __float_as_uint(srow[p + off[s][0]]);
                a[1] = __float_as_uint(srow[p + 8 + off[s][0]]);
                a[2] = __float_as_uint(srow[p + off[s][1]]);
                a[3] = __float_as_uint(srow[p + 8 + off[s][1]]);
                mma_tf32(acc[0], a, bf[s][0][0], bf[s][0][1]);
                mma_tf32(acc[1], a, bf[s][1][0], bf[s][1][1]);
            }
            {   // s = 3: only tap 24 (tg==0); cols 25..31 zero
                uint32_t a[4];
                a[0] = t24 ? __float_as_uint(srow[p + off[3][0]]) : 0u;
                a[1] = t24 ? __float_as_uint(srow[p + 8 + off[3][0]]) : 0u;
                a[2] = 0u;
                a[3] = 0u;
                mma_tf32(acc[0], a, bf[3][0][0], bf[3][0][1]);
                mma_tf32(acc[1], a, bf[3][1][0], bf[3][1][1]);
            }

            // ---- STS to bounce buffer (conflict-free: banks (8tg+g)%32) ----
            const int px = ct * 16 + g;
            bw[(2 * tg)     * BSTRIDE + px]     = acc[0][0];
            bw[(2 * tg + 1) * BSTRIDE + px]     = acc[0][1];
            bw[(2 * tg)     * BSTRIDE + px + 8] = acc[0][2];
            bw[(2 * tg + 1) * BSTRIDE + px + 8] = acc[0][3];
            if (tg == 0) {   // n = 8, 9
                bw[8 * BSTRIDE + px]     = acc[1][0];
                bw[9 * BSTRIDE + px]     = acc[1][1];
                bw[8 * BSTRIDE + px + 8] = acc[1][2];
                bw[9 * BSTRIDE + px + 8] = acc[1][3];
            }
        }
        __syncwarp();

        // ---- coalesced emit: one LDS.128 + STG.128 per n-plane ----
        float* orow = outbc + (size_t)lr * Wv + lane * 4;
        #pragma unroll
        for (int n = 0; n < Nv; n++) {
            float4 v = *reinterpret_cast<const float4*>(&bw[n * BSTRIDE + lane * 4]);
            *reinterpret_cast<float4*>(orow + (size_t)n * ns) = v;
        }
        __syncwarp();
    }
}

extern "C" void kernel_launch(void* const* d_in, const int* in_sizes, int n_in,
                              void* d_out, int out_size)
{
    const float* images  = (const float*)d_in[0];   // [B,H,W,C]
    const float* kernels = (const float*)d_in[1];   // [B,KH,KW,N]
    float* out = (float*)d_out;                     // [N,B,C,H,W]

    dim3 block(NT, 1, 1);
    dim3 grid(Hv / ROWS, Cv, Bv);   // (16, 3, 64)
    cdna_mma_kernel<<<grid, block>>>(images, kernels, out);
}

// round 8
// speedup vs baseline: 1.2358x; 1.2358x over previous
#include <cuda_runtime.h>
#include <cstdint>

// Problem dims (fixed)
#define Bv 64
#define Hv 128
#define Wv 128
#define Cv 3
#define Nv 10

#define ROWS 32                // output rows per CTA
#define SRR (ROWS + 4)         // 36 strip rows
#define PXB 64                 // pixels (width) per CTA
#define SCV (PXB + 4)          // 68 valid strip cols
#define SST 76                 // padded strip stride (76 % 32 = 12, conflict-free)
#define NT 128                 // 4 warps, one 16-px col tile each

__device__ __forceinline__ uint32_t to_tf32(float v) {
    uint32_t u;
    asm("cvt.rna.tf32.f32 %0, %1;" : "=r"(u) : "f"(v));
    return u;
}

__device__ __forceinline__ void mma_tf32(float c[4], const uint32_t a[4],
                                         uint32_t b0, uint32_t b1) {
    asm("mma.sync.aligned.m16n8k8.row.col.f32.tf32.tf32.f32 "
        "{%0,%1,%2,%3}, {%4,%5,%6,%7}, {%8,%9}, {%0,%1,%2,%3};"
        : "+f"(c[0]), "+f"(c[1]), "+f"(c[2]), "+f"(c[3])
        : "r"(a[0]), "r"(a[1]), "r"(a[2]), "r"(a[3]), "r"(b0), "r"(b1));
}

// out[n][b][c][h][w] = sum_{kh,kw} images[b][h+kh-2][w+kw-2][c] * kernels[b][kh][kw][n]
// K laid out kh-major: k = 8*kh + kw (kw slots 5..7 zero). One strip-row fragment
// serves all 5 kh-groups (for output rows ai-0 .. ai-4) -> 4 LDS feed 10 MMAs.
__global__ __launch_bounds__(NT, 5)
void cdna_mma_kernel(const float* __restrict__ images,
                     const float* __restrict__ kernels,
                     float* __restrict__ out)
{
    __shared__ float strip[SRR * SST];   // tf32-rounded image strip
    __shared__ float Wsm[40][16];        // tf32-rounded weights [k=8kh+kw][n]

    const int tid  = threadIdx.x;
    const int lane = tid & 31;
    const int wrp  = tid >> 5;         // 0..3: 16-px column tile
    const int g    = lane >> 2;        // 0..7
    const int tg   = lane & 3;         // 0..3
    const bool t24 = (tg == 0);

    const int bx = blockIdx.x & 1;     // width half
    const int rt = blockIdx.x >> 1;    // row tile 0..3
    const int c  = blockIdx.y;
    const int b  = blockIdx.z;
    const int r0 = rt * ROWS;
    const int px0 = bx * PXB;

    // ---- stage W: [k=40][n=16], kh-major slots, tf32-rounded, pad -> 0 ----
    for (int i = tid; i < 640; i += NT) {
        int k = i >> 4, n = i & 15;
        int s = k >> 3, t = k & 7;
        float v = 0.0f;
        if (t < 5 && n < Nv) v = kernels[(b * 25 + s * 5 + t) * Nv + n];
        Wsm[k][n] = __uint_as_float(to_tf32(v));
    }

    // ---- stage image strip (tf32-rounded, zero-padded halo) ----
    const float* imgb = images + ((size_t)b * Hv) * (Wv * Cv) + c;
    #pragma unroll
    for (int it = 0; it < (SRR * SCV + NT - 1) / NT; it++) {
        int i = it * NT + tid;
        if (i < SRR * SCV) {
            int r  = i / SCV;
            int cc = i - r * SCV;
            int gh = r0 + r - 2;
            int gw = px0 + cc - 2;
            float v = 0.0f;
            if (gh >= 0 && gh < Hv && gw >= 0 && gw < Wv)
                v = imgb[(gh * Wv + gw) * Cv];
            strip[r * SST + cc] = __uint_as_float(to_tf32(v));
        }
    }
    __syncthreads();

    // ---- B fragments: bf[s=kh][u][j] ----
    uint32_t bf[5][2][2];
    #pragma unroll
    for (int s = 0; s < 5; s++)
        #pragma unroll
        for (int u = 0; u < 2; u++) {
            bf[s][u][0] = __float_as_uint(Wsm[8 * s + tg][8 * u + g]);
            bf[s][u][1] = __float_as_uint(Wsm[8 * s + tg + 4][8 * u + g]);
        }

    const int x = wrp * 16 + g;        // A-row m=g pixel (m=g+8 -> x+8)
    const size_t ns = (size_t)Bv * Cv * Hv * Wv;
    float* outbc = out + (((size_t)b * Cv + c) * Hv + r0) * Wv + px0;

    // ---- 5-row accumulator ring; walk 36 strip rows ----
    float acc[5][2][4] = {};

    #pragma unroll
    for (int ai = 0; ai < SRR; ai++) {
        const float* sr = strip + ai * SST + x;
        uint32_t a[4];
        a[0] = __float_as_uint(sr[tg]);
        a[1] = __float_as_uint(sr[8 + tg]);
        float v2 = sr[4], v3 = sr[12];
        a[2] = t24 ? __float_as_uint(v2) : 0u;
        a[3] = t24 ? __float_as_uint(v3) : 0u;

        #pragma unroll
        for (int s = 0; s < 5; s++) {
            const int r = ai - s;
            if (r >= 0 && r < ROWS) {
                const int sl = r % 5;
                mma_tf32(acc[sl][0], a, bf[s][0][0], bf[s][0][1]);
                mma_tf32(acc[sl][1], a, bf[s][1][0], bf[s][1][1]);
            }
        }

        const int rd = ai - 4;          // completed output row
        if (rd >= 0) {
            const int sl = rd % 5;
            float* orow = outbc + (size_t)rd * Wv + wrp * 16 + g;
            orow[(size_t)(2 * tg)     * ns]     = acc[sl][0][0];
            orow[(size_t)(2 * tg + 1) * ns]     = acc[sl][0][1];
            orow[(size_t)(2 * tg)     * ns + 8] = acc[sl][0][2];
            orow[(size_t)(2 * tg + 1) * ns + 8] = acc[sl][0][3];
            if (t24) {                   // n = 8, 9
                orow[8 * ns]     = acc[sl][1][0];
                orow[9 * ns]     = acc[sl][1][1];
                orow[8 * ns + 8] = acc[sl][1][2];
                orow[9 * ns + 8] = acc[sl][1][3];
            }
            #pragma unroll
            for (int u = 0; u < 2; u++)
                #pragma unroll
                for (int q = 0; q < 4; q++)
                    acc[sl][u][q] = 0.0f;
        }
    }
}

extern "C" void kernel_launch(void* const* d_in, const int* in_sizes, int n_in,
                              void* d_out, int out_size)
{
    const float* images  = (const float*)d_in[0];   // [B,H,W,C]
    const float* kernels = (const float*)d_in[1];   // [B,KH,KW,N]
    float* out = (float*)d_out;                     // [N,B,C,H,W]

    dim3 block(NT, 1, 1);
    dim3 grid((Wv / PXB) * (Hv / ROWS), Cv, Bv);   // (8, 3, 64)
    cdna_mma_kernel<<<grid, block>>>(images, kernels, out);
}